// round 13
// baseline (speedup 1.0000x reference)
#include <cuda_runtime.h>
#include <cuda_fp16.h>
#include <cstdint>
#include <cstddef>

// ---------------------------------------------------------------------------
// BiMiniGRU: B=8, L=8192, C=D=256
//   proj: 6x GEMM [65536,256]x[256,256] + bias (+sigmoid on z,s)
//         fp16 mma.sync (f32 accum), plain PTX (compute_103-legal)
//   One CTA = (128-row M-tile, direction); 128 threads, warp tile 64x64.
//   A resident fp16 in SMEM (64KB); fused scan pass1 (32-step segments).
//   scan: h[t] = (1-z)*h[t-1] + z*h~[t]; out = h_f*s_f + h_b*s_b
// ---------------------------------------------------------------------------

#define BSZ 8
#define LSZ 8192
#define DSZ 256
#define MSZ (BSZ * LSZ)          // 65536
#define MT  128                  // M tile rows
#define SEGL 32                  // scan segment length
#define NSEG2 256                // segments per direction (LSZ/SEGL)

// SMEM: A 4 chunks x 16KB (128 rows x 64 k fp16, SW128) + B 3 stages x 16KB
#define SM_A 0
#define SM_B 65536
#define GEMM_SMEM (65536 + 3 * 16384)    // 114688 -> 2 CTAs/SM

#define SW128(o) ((o) ^ (((o) >> 3) & 0x70))

// ---------------------------------------------------------------------------
// Scratch (__device__ globals; allocation-free rule)
// widx order: 0=z_f, 1=h~_f, 2=s_f, 3=z_b, 4=h~_b, 5=s_b   (fp16 storage)
// ---------------------------------------------------------------------------
__device__ __align__(16) __half g_proj[6][(size_t)MSZ * DSZ];
__device__ __align__(16) __half g_wT[6][DSZ * DSZ];
__device__ float g_segA[2 * BSZ * NSEG2 * DSZ];
__device__ float g_segB[2 * BSZ * NSEG2 * DSZ];
__device__ float g_carry[2 * BSZ * NSEG2 * DSZ];

// ---------------------------------------------------------------------------
// PTX helpers (plain PTX only)
// ---------------------------------------------------------------------------
__device__ __forceinline__ uint32_t smem_u32(const void* p) {
    uint32_t a;
    asm("{ .reg .u64 t; cvta.to.shared.u64 t, %1; cvt.u32.u64 %0, t; }"
        : "=r"(a) : "l"(p));
    return a;
}

#define CP16(dst, src) asm volatile( \
    "cp.async.cg.shared.global [%0], [%1], 16;" :: "r"(dst), "l"(src))
#define CP_COMMIT() asm volatile("cp.async.commit_group;" ::: "memory")
#define CP_WAIT1()  asm volatile("cp.async.wait_group 1;" ::: "memory")

#define LDSM_X4(r, addr) asm volatile( \
    "ldmatrix.sync.aligned.m8n8.x4.shared.b16 {%0,%1,%2,%3}, [%4];" \
    : "=r"((r)[0]), "=r"((r)[1]), "=r"((r)[2]), "=r"((r)[3]) : "r"(addr))

#define MMA_F16_P(cc, a, b0, b1) asm volatile( \
    "mma.sync.aligned.m16n8k16.row.col.f32.f16.f16.f32 " \
    "{%0,%1,%2,%3}, {%4,%5,%6,%7}, {%8,%9}, {%0,%1,%2,%3};" \
    : "+f"((cc)[0]), "+f"((cc)[1]), "+f"((cc)[2]), "+f"((cc)[3]) \
    : "r"((a)[0]), "r"((a)[1]), "r"((a)[2]), "r"((a)[3]), \
      "r"(b0), "r"(b1))

// ---------------------------------------------------------------------------
// Precompute: W^T (n-major rows of k) fp16 per weight
// ---------------------------------------------------------------------------
struct WPtrs { const float* W[6]; };
__global__ void prep_w(WPtrs wp) {
    int widx = blockIdx.x;
    int n = blockIdx.y;
    int k = threadIdx.x;
    g_wT[widx][n * DSZ + k] = __float2half_rn(wp.W[widx][(size_t)k * DSZ + n]);
}

// ---------------------------------------------------------------------------
// Fused projection kernel. grid (512 tiles, 2 dirs), 128 threads
// (4 warps 2m x 2n; warp tile 64x64). A resident; 3 weights x 2 nh x 4 kc.
// Epilogue: bias+activation fp16 stores; then fused pass1 (four 32-parts).
// ---------------------------------------------------------------------------
struct BiasPtrs { const float* b[6]; };

__global__ __launch_bounds__(128, 2)
void gemm_fused(BiasPtrs gb, const float* __restrict__ xs) {
    extern __shared__ __align__(128) char sm[];
    uint32_t sbase = smem_u32(sm);

    const int m0   = blockIdx.x * MT;
    const int dir  = blockIdx.y;
    const int t    = threadIdx.x;
    const int lane = t & 31;
    const int wid  = t >> 5;
    const int wm   = (wid & 1) * 64;
    const int wn   = (wid >> 1) * 64;

    // ---- B chunk loader: q = (wl*2 + nh)*4 + kc, stage = q % 3 ----
    auto loadB = [&](int q) {
        const int wl = q >> 3;
        const int nh = (q >> 2) & 1;
        const int kc = q & 3;
        const __half* __restrict__ Bp = g_wT[dir * 3 + wl];
        uint32_t so = sbase + SM_B + (q % 3) * 16384;
        #pragma unroll
        for (int it = 0; it < 8; it++) {
            int seg = t + it * 128;
            int row = seg >> 3;              // 0..127 (n within half)
            int u   = seg & 7;               // 16B unit in 128B row
            uint32_t sw = SW128((uint32_t)(row * 128 + u * 16));
            CP16(so + sw, Bp + (size_t)(nh * 128 + row) * DSZ + kc * 64 + u * 8);
        }
    };

    loadB(0); CP_COMMIT();
    loadB(1); CP_COMMIT();

    // ---- load + convert the A tile (128 rows x 256 k fp16) ----
    {
        const float4* X4 = reinterpret_cast<const float4*>(xs);
        // 128 rows x 64 float4 = 8192 items; 128 threads x 64 iters
        #pragma unroll 8
        for (int it = 0; it < 64; it++) {
            int g   = t + it * 128;          // 0..8191
            int row = g >> 6;                // 0..127
            int f4  = g & 63;                // float4 within 256-float row
            float4 v = X4[(size_t)(m0 + row) * 64 + f4];
            __half2 p01 = __floats2half2_rn(v.x, v.y);
            __half2 p23 = __floats2half2_rn(v.z, v.w);
            uint2 u2;
            u2.x = *reinterpret_cast<uint32_t*>(&p01);
            u2.y = *reinterpret_cast<uint32_t*>(&p23);
            int chunk = f4 >> 4;             // k-chunk of 64
            uint32_t sw = SW128((uint32_t)(row * 128 + (f4 & 15) * 8));
            *reinterpret_cast<uint2*>(sm + SM_A + chunk * 16384 + sw) = u2;
        }
    }

    const int gg = lane >> 3, r = lane & 7;

    // ---- main loop: 3 weights x 2 n-halves x 4 k-chunks (24 iters) ----
    int q = 0;
    for (int wl = 0; wl < 3; wl++) {
        const bool do_sig = (wl != 1);       // z, s sigmoid; h~ raw
        const float* __restrict__ bias = gb.b[dir * 3 + wl];
        __half* __restrict__ Out = g_proj[dir * 3 + wl];
        for (int nh = 0; nh < 2; nh++) {
            float c[4][8][4];
            #pragma unroll
            for (int mi = 0; mi < 4; mi++)
                #pragma unroll
                for (int nj = 0; nj < 8; nj++)
                    #pragma unroll
                    for (int p = 0; p < 4; p++) c[mi][nj][p] = 0.0f;

            for (int kc = 0; kc < 4; kc++, q++) {
                CP_WAIT1();                  // group q complete
                __syncthreads();             // visibility + prev compute done
                if (q + 2 < 24) loadB(q + 2);
                CP_COMMIT();

                uint32_t sa = sbase + SM_A + kc * 16384;
                uint32_t sb = sbase + SM_B + (q % 3) * 16384;
                #pragma unroll
                for (int ks = 0; ks < 4; ks++) {
                    // A x4: groups {m0-7:k0, m8-15:k0, m0-7:k8, m8-15:k8}
                    uint32_t aoff = SW128((uint32_t)(
                        (wm + (gg & 1) * 8 + r) * 128 + (ks * 16 + (gg >> 1) * 8) * 2));
                    // B x4: groups {n8_0:k0, n8_0:k8, n8_1:k0, n8_1:k8}
                    uint32_t boff = SW128((uint32_t)(
                        (wn + (gg >> 1) * 8 + r) * 128 + (ks * 16 + (gg & 1) * 8) * 2));
                    uint32_t af[4][4], bf[4][4];
                    #pragma unroll
                    for (int mi = 0; mi < 4; mi++)
                        LDSM_X4(af[mi], sa + aoff + mi * 2048);
                    #pragma unroll
                    for (int ni = 0; ni < 4; ni++)
                        LDSM_X4(bf[ni], sb + boff + ni * 2048);
                    #pragma unroll
                    for (int mi = 0; mi < 4; mi++)
                        #pragma unroll
                        for (int ni = 0; ni < 4; ni++) {
                            MMA_F16_P(c[mi][2 * ni],     af[mi], bf[ni][0], bf[ni][1]);
                            MMA_F16_P(c[mi][2 * ni + 1], af[mi], bf[ni][2], bf[ni][3]);
                        }
                }
            }

            // ---- epilogue for this (wl, nh): bias, act, fp16 store ----
            #pragma unroll
            for (int nj = 0; nj < 8; nj++) {
                const int col = nh * 128 + wn + nj * 8 + (lane & 3) * 2;
                const float2 bb = *reinterpret_cast<const float2*>(bias + col);
                #pragma unroll
                for (int mi = 0; mi < 4; mi++) {
                    const int row = m0 + wm + mi * 16 + (lane >> 2);
                    float v0 = c[mi][nj][0] + bb.x;
                    float v1 = c[mi][nj][1] + bb.y;
                    float v2 = c[mi][nj][2] + bb.x;
                    float v3 = c[mi][nj][3] + bb.y;
                    if (do_sig) {
                        v0 = 1.0f / (1.0f + __expf(-v0));
                        v1 = 1.0f / (1.0f + __expf(-v1));
                        v2 = 1.0f / (1.0f + __expf(-v2));
                        v3 = 1.0f / (1.0f + __expf(-v3));
                    }
                    *reinterpret_cast<__half2*>(Out + (size_t)row * DSZ + col)
                        = __floats2half2_rn(v0, v1);
                    *reinterpret_cast<__half2*>(Out + (size_t)(row + 8) * DSZ + col)
                        = __floats2half2_rn(v2, v3);
                }
            }
        }
    }

    // ---- fused pass1: four 32-step segment maps, this dir, half2 lanes ----
    __syncthreads();   // all global stores of this CTA visible block-wide
    const int d2  = t;                        // channel pair 2*d2, 2*d2+1
    const int b   = m0 >> 13;                 // batch
    const int s32 = (m0 & (LSZ - 1)) >> 5;    // first 32-seg index
    const __half2* __restrict__ Z = reinterpret_cast<const __half2*>(g_proj[dir * 3 + 0]);
    const __half2* __restrict__ H = reinterpret_cast<const __half2*>(g_proj[dir * 3 + 1]);

    #pragma unroll
    for (int part = 0; part < 4; part++) {
        float2 A; A.x = 1.0f; A.y = 1.0f;
        float2 Bc; Bc.x = 0.0f; Bc.y = 0.0f;
        #pragma unroll 4
        for (int i = 0; i < SEGL; i++) {
            int rr = dir ? (SEGL - 1 - i) : i;   // bwd composes descending
            size_t idx = (size_t)(m0 + part * SEGL + rr) * 128 + d2;
            float2 z  = __half22float2(Z[idx]);
            float2 ht = __half22float2(H[idx]);
            float ax = 1.0f - z.x, ay = 1.0f - z.y;
            A.x *= ax;  A.y *= ay;
            Bc.x = fmaf(ax, Bc.x, z.x * ht.x);
            Bc.y = fmaf(ay, Bc.y, z.y * ht.y);
        }
        int segidx = dir ? (NSEG2 - 1 - (s32 + part)) : (s32 + part);
        size_t o = (((size_t)dir * BSZ + b) * NSEG2 + segidx) * DSZ + 2 * d2;
        *reinterpret_cast<float2*>(&g_segA[o]) = A;
        *reinterpret_cast<float2*>(&g_segB[o]) = Bc;
    }
}

// ---------------------------------------------------------------------------
// Scan pass 2: sequential combine over 256 segments; register-batched.
// grid (BSZ, 2), block DSZ
// ---------------------------------------------------------------------------
__global__ void scan_pass2(const float* __restrict__ h0f,
                           const float* __restrict__ h0b) {
    const int d   = threadIdx.x;
    const int b   = blockIdx.x;
    const int dir = blockIdx.y;
    float h = dir ? h0b[d] : h0f[d];
    size_t base = (((size_t)dir * BSZ + b) * NSEG2) * DSZ + d;
    for (int sc = 0; sc < NSEG2 / 16; sc++) {
        float rA[16], rB[16];
        #pragma unroll
        for (int s = 0; s < 16; s++) {
            size_t o = base + (size_t)(sc * 16 + s) * DSZ;
            rA[s] = g_segA[o];
            rB[s] = g_segB[o];
        }
        #pragma unroll
        for (int s = 0; s < 16; s++) {
            size_t o = base + (size_t)(sc * 16 + s) * DSZ;
            g_carry[o] = h;
            h = fmaf(rA[s], h, rB[s]);
        }
    }
}

// ---------------------------------------------------------------------------
// Scan out: both directions fused; fwd staged as fp16 in 16KB SMEM.
// grid (NSEG2, BSZ), block 128 (each thread owns 2 adjacent d channels)
// ---------------------------------------------------------------------------
__global__ void scan_out(float* __restrict__ out) {
    extern __shared__ __half2 sv[];           // [SEGL][128]
    const int d2  = threadIdx.x;              // channel pair: d = 2*d2, 2*d2+1
    const int seg = blockIdx.x;
    const int b   = blockIdx.y;
    const __half2* __restrict__ Zf = reinterpret_cast<const __half2*>(g_proj[0]);
    const __half2* __restrict__ Hf = reinterpret_cast<const __half2*>(g_proj[1]);
    const __half2* __restrict__ Sf = reinterpret_cast<const __half2*>(g_proj[2]);
    const __half2* __restrict__ Zb = reinterpret_cast<const __half2*>(g_proj[3]);
    const __half2* __restrict__ Hb = reinterpret_cast<const __half2*>(g_proj[4]);
    const __half2* __restrict__ Sb = reinterpret_cast<const __half2*>(g_proj[5]);

    // half2-granular row base: row * 128 + d2
    size_t rowbase = ((size_t)b * LSZ + (size_t)seg * SEGL) * 128 + d2;

    // forward
    float2 h = *reinterpret_cast<const float2*>(
        &g_carry[(((size_t)b) * NSEG2 + seg) * DSZ + 2 * d2]);
    #pragma unroll 4
    for (int i = 0; i < SEGL; i++) {
        size_t idx = rowbase + (size_t)i * 128;
        float2 z = __half22float2(Zf[idx]);
        float2 ht = __half22float2(Hf[idx]);
        float2 s = __half22float2(Sf[idx]);
        h.x = fmaf(1.0f - z.x, h.x, z.x * ht.x);
        h.y = fmaf(1.0f - z.y, h.y, z.y * ht.y);
        sv[i * 128 + d2] = __floats2half2_rn(h.x * s.x, h.y * s.y);
    }
    // backward: these rows reversed form bwd segment NSEG2-1-seg
    float2 hb = *reinterpret_cast<const float2*>(
        &g_carry[(((size_t)BSZ + b) * NSEG2 + (NSEG2 - 1 - seg)) * DSZ + 2 * d2]);
    #pragma unroll 4
    for (int jj = 0; jj < SEGL; jj++) {
        int i = SEGL - 1 - jj;
        size_t idx = rowbase + (size_t)i * 128;
        float2 z = __half22float2(Zb[idx]);
        float2 ht = __half22float2(Hb[idx]);
        float2 s = __half22float2(Sb[idx]);
        hb.x = fmaf(1.0f - z.x, hb.x, z.x * ht.x);
        hb.y = fmaf(1.0f - z.y, hb.y, z.y * ht.y);
        float2 v = __half22float2(sv[i * 128 + d2]);
        v.x = fmaf(hb.x, s.x, v.x);
        v.y = fmaf(hb.y, s.y, v.y);
        *reinterpret_cast<float2*>(&out[idx * 2]) = v;
    }
}

// ---------------------------------------------------------------------------
// Launch. Inputs: 0 xs, 1 Wh1, 2 bh1, 3 Wz1, 4 bz1, 5 Ws1, 6 bs1, 7 h01,
//   8 Wh_1, 9 bh_1, 10 Wz_1, 11 bz_1, 12 Ws_1, 13 bs_1, 14 h0_1
// ---------------------------------------------------------------------------
extern "C" void kernel_launch(void* const* d_in, const int* in_sizes, int n_in,
                              void* d_out, int out_size) {
    cudaFuncSetAttribute(gemm_fused,
                         cudaFuncAttributeMaxDynamicSharedMemorySize, GEMM_SMEM);

    // widx: 0=z_f(Wz1), 1=h_f(Wh1), 2=s_f(Ws1), 3=z_b(Wz_1), 4=h_b(Wh_1), 5=s_b(Ws_1)
    WPtrs wp;
    wp.W[0] = (const float*)d_in[3];
    wp.W[1] = (const float*)d_in[1];
    wp.W[2] = (const float*)d_in[5];
    wp.W[3] = (const float*)d_in[10];
    wp.W[4] = (const float*)d_in[8];
    wp.W[5] = (const float*)d_in[12];
    BiasPtrs bp;
    bp.b[0] = (const float*)d_in[4];
    bp.b[1] = (const float*)d_in[2];
    bp.b[2] = (const float*)d_in[6];
    bp.b[3] = (const float*)d_in[11];
    bp.b[4] = (const float*)d_in[9];
    bp.b[5] = (const float*)d_in[13];

    prep_w<<<dim3(6, 256), 256>>>(wp);
    gemm_fused<<<dim3(MSZ / MT, 2), 128, GEMM_SMEM>>>(bp, (const float*)d_in[0]);
    scan_pass2<<<dim3(BSZ, 2), DSZ>>>((const float*)d_in[7], (const float*)d_in[14]);
    scan_out<<<dim3(NSEG2, BSZ), 128, SEGL * 128 * sizeof(__half2)>>>((float*)d_out);
}

// round 14
// speedup vs baseline: 1.2064x; 1.2064x over previous
#include <cuda_runtime.h>
#include <cuda_fp16.h>
#include <cstdint>
#include <cstddef>

// ---------------------------------------------------------------------------
// BiMiniGRU: B=8, L=8192, C=D=256
//   proj: 6x GEMM [65536,256]x[256,256] + bias (+sigmoid on z,s)
//         fp16 mma.sync (f32 accum), plain PTX (compute_103-legal)
//   One CTA = (128-row M-tile, direction); 256 threads, warp tile 64x32.
//   A resident fp16 in SMEM (64KB); fused scan pass1 (32-step segments).
//   scan: h[t] = (1-z)*h[t-1] + z*h~[t]; out = h_f*s_f + h_b*s_b
// ---------------------------------------------------------------------------

#define BSZ 8
#define LSZ 8192
#define DSZ 256
#define MSZ (BSZ * LSZ)          // 65536
#define MT  128                  // M tile rows
#define SEGL 32                  // scan segment length
#define NSEG2 256                // segments per direction (LSZ/SEGL)

// SMEM: A 4 chunks x 16KB (128 rows x 64 k fp16, SW128) + B 3 stages x 16KB
#define SM_A 0
#define SM_B 65536
#define GEMM_SMEM (65536 + 3 * 16384)    // 114688 -> 2 CTAs/SM

#define SW128(o) ((o) ^ (((o) >> 3) & 0x70))

// ---------------------------------------------------------------------------
// Scratch (__device__ globals; allocation-free rule)
// widx order: 0=z_f, 1=h~_f, 2=s_f, 3=z_b, 4=h~_b, 5=s_b   (fp16 storage)
// ---------------------------------------------------------------------------
__device__ __align__(16) __half g_proj[6][(size_t)MSZ * DSZ];
__device__ __align__(16) __half g_wT[6][DSZ * DSZ];
__device__ float g_segA[2 * BSZ * NSEG2 * DSZ];
__device__ float g_segB[2 * BSZ * NSEG2 * DSZ];
__device__ float g_carry[2 * BSZ * NSEG2 * DSZ];

// ---------------------------------------------------------------------------
// PTX helpers (plain PTX only)
// ---------------------------------------------------------------------------
__device__ __forceinline__ uint32_t smem_u32(const void* p) {
    uint32_t a;
    asm("{ .reg .u64 t; cvta.to.shared.u64 t, %1; cvt.u32.u64 %0, t; }"
        : "=r"(a) : "l"(p));
    return a;
}

#define CP16(dst, src) asm volatile( \
    "cp.async.cg.shared.global [%0], [%1], 16;" :: "r"(dst), "l"(src))
#define CP_COMMIT() asm volatile("cp.async.commit_group;" ::: "memory")
#define CP_WAIT1()  asm volatile("cp.async.wait_group 1;" ::: "memory")

#define LDSM_X4(r, addr) asm volatile( \
    "ldmatrix.sync.aligned.m8n8.x4.shared.b16 {%0,%1,%2,%3}, [%4];" \
    : "=r"((r)[0]), "=r"((r)[1]), "=r"((r)[2]), "=r"((r)[3]) : "r"(addr))

#define MMA_F16_P(cc, a, b0, b1) asm volatile( \
    "mma.sync.aligned.m16n8k16.row.col.f32.f16.f16.f32 " \
    "{%0,%1,%2,%3}, {%4,%5,%6,%7}, {%8,%9}, {%0,%1,%2,%3};" \
    : "+f"((cc)[0]), "+f"((cc)[1]), "+f"((cc)[2]), "+f"((cc)[3]) \
    : "r"((a)[0]), "r"((a)[1]), "r"((a)[2]), "r"((a)[3]), \
      "r"(b0), "r"(b1))

// ---------------------------------------------------------------------------
// Precompute: W^T (n-major rows of k) fp16 per weight
// ---------------------------------------------------------------------------
struct WPtrs { const float* W[6]; };
__global__ void prep_w(WPtrs wp) {
    int widx = blockIdx.x;
    int n = blockIdx.y;
    int k = threadIdx.x;
    g_wT[widx][n * DSZ + k] = __float2half_rn(wp.W[widx][(size_t)k * DSZ + n]);
}

// ---------------------------------------------------------------------------
// Fused projection kernel. grid (512 tiles, 2 dirs), 256 threads
// (8 warps 2m x 4n; warp tile 64x32). A resident; 3 weights x 2 nh x 4 kc.
// B fragments via ldmatrix.x4 (6 LDSM per 16 HMMA per k-step).
// Epilogue: bias+activation fp16 stores; then fused pass1 (four 32-parts).
// ---------------------------------------------------------------------------
struct BiasPtrs { const float* b[6]; };

__global__ __launch_bounds__(256, 2)
void gemm_fused(BiasPtrs gb, const float* __restrict__ xs) {
    extern __shared__ __align__(128) char sm[];
    uint32_t sbase = smem_u32(sm);

    const int m0   = blockIdx.x * MT;
    const int dir  = blockIdx.y;
    const int t    = threadIdx.x;
    const int lane = t & 31;
    const int wid  = t >> 5;
    const int wm   = (wid & 1) * 64;
    const int wn   = (wid >> 1) * 32;

    // ---- B chunk loader: q = (wl*2 + nh)*4 + kc, stage = q % 3 ----
    auto loadB = [&](int q) {
        const int wl = q >> 3;
        const int nh = (q >> 2) & 1;
        const int kc = q & 3;
        const __half* __restrict__ Bp = g_wT[dir * 3 + wl];
        uint32_t so = sbase + SM_B + (q % 3) * 16384;
        #pragma unroll
        for (int it = 0; it < 4; it++) {
            int seg = t + it * 256;
            int row = seg >> 3;              // 0..127 (n within half)
            int u   = seg & 7;               // 16B unit in 128B row
            uint32_t sw = SW128((uint32_t)(row * 128 + u * 16));
            CP16(so + sw, Bp + (size_t)(nh * 128 + row) * DSZ + kc * 64 + u * 8);
        }
    };

    loadB(0); CP_COMMIT();
    loadB(1); CP_COMMIT();

    // ---- load + convert the A tile (128 rows x 256 k fp16) ----
    {
        const float4* X4 = reinterpret_cast<const float4*>(xs);
        // 128 rows x 64 float4 = 8192 items; 256 threads x 32 iters
        #pragma unroll 8
        for (int it = 0; it < 32; it++) {
            int g   = t + it * 256;          // 0..8191
            int row = g >> 6;                // 0..127
            int f4  = g & 63;                // float4 within 256-float row
            float4 v = X4[(size_t)(m0 + row) * 64 + f4];
            __half2 p01 = __floats2half2_rn(v.x, v.y);
            __half2 p23 = __floats2half2_rn(v.z, v.w);
            uint2 u2;
            u2.x = *reinterpret_cast<uint32_t*>(&p01);
            u2.y = *reinterpret_cast<uint32_t*>(&p23);
            int chunk = f4 >> 4;             // k-chunk of 64
            uint32_t sw = SW128((uint32_t)(row * 128 + (f4 & 15) * 8));
            *reinterpret_cast<uint2*>(sm + SM_A + chunk * 16384 + sw) = u2;
        }
    }

    const int gg = lane >> 3, r = lane & 7;

    // ---- main loop: 3 weights x 2 n-halves x 4 k-chunks (24 iters) ----
    int q = 0;
    for (int wl = 0; wl < 3; wl++) {
        const bool do_sig = (wl != 1);       // z, s sigmoid; h~ raw
        const float* __restrict__ bias = gb.b[dir * 3 + wl];
        __half* __restrict__ Out = g_proj[dir * 3 + wl];
        for (int nh = 0; nh < 2; nh++) {
            float c[4][4][4];
            #pragma unroll
            for (int mi = 0; mi < 4; mi++)
                #pragma unroll
                for (int ni = 0; ni < 4; ni++)
                    #pragma unroll
                    for (int p = 0; p < 4; p++) c[mi][ni][p] = 0.0f;

            for (int kc = 0; kc < 4; kc++, q++) {
                CP_WAIT1();                  // group q complete
                __syncthreads();             // visibility + prev compute done
                if (q + 2 < 24) loadB(q + 2);
                CP_COMMIT();

                uint32_t sa = sbase + SM_A + kc * 16384;
                uint32_t sb = sbase + SM_B + (q % 3) * 16384;
                #pragma unroll
                for (int ks = 0; ks < 4; ks++) {
                    // A x4: groups {m0-7:k0, m8-15:k0, m0-7:k8, m8-15:k8}
                    uint32_t aoff = SW128((uint32_t)(
                        (wm + (gg & 1) * 8 + r) * 128 + (ks * 16 + (gg >> 1) * 8) * 2));
                    // B x4: groups {n8_0:k0, n8_0:k8, n8_1:k0, n8_1:k8}
                    uint32_t boff = SW128((uint32_t)(
                        (wn + (gg >> 1) * 8 + r) * 128 + (ks * 16 + (gg & 1) * 8) * 2));
                    uint32_t af[4][4], bf[2][4];
                    #pragma unroll
                    for (int mi = 0; mi < 4; mi++)
                        LDSM_X4(af[mi], sa + aoff + mi * 2048);
                    #pragma unroll
                    for (int ni = 0; ni < 2; ni++)
                        LDSM_X4(bf[ni], sb + boff + ni * 2048);
                    #pragma unroll
                    for (int mi = 0; mi < 4; mi++)
                        #pragma unroll
                        for (int ni = 0; ni < 2; ni++) {
                            MMA_F16_P(c[mi][2 * ni],     af[mi], bf[ni][0], bf[ni][1]);
                            MMA_F16_P(c[mi][2 * ni + 1], af[mi], bf[ni][2], bf[ni][3]);
                        }
                }
            }

            // ---- epilogue for this (wl, nh): bias, act, fp16 store ----
            #pragma unroll
            for (int ni = 0; ni < 4; ni++) {
                const int col = nh * 128 + wn + ni * 8 + (lane & 3) * 2;
                const float2 bb = *reinterpret_cast<const float2*>(bias + col);
                #pragma unroll
                for (int mi = 0; mi < 4; mi++) {
                    const int row = m0 + wm + mi * 16 + (lane >> 2);
                    float v0 = c[mi][ni][0] + bb.x;
                    float v1 = c[mi][ni][1] + bb.y;
                    float v2 = c[mi][ni][2] + bb.x;
                    float v3 = c[mi][ni][3] + bb.y;
                    if (do_sig) {
                        v0 = 1.0f / (1.0f + __expf(-v0));
                        v1 = 1.0f / (1.0f + __expf(-v1));
                        v2 = 1.0f / (1.0f + __expf(-v2));
                        v3 = 1.0f / (1.0f + __expf(-v3));
                    }
                    *reinterpret_cast<__half2*>(Out + (size_t)row * DSZ + col)
                        = __floats2half2_rn(v0, v1);
                    *reinterpret_cast<__half2*>(Out + (size_t)(row + 8) * DSZ + col)
                        = __floats2half2_rn(v2, v3);
                }
            }
        }
    }

    // ---- fused pass1: four 32-step segment affine maps, this dir ----
    __syncthreads();   // all global stores of this CTA visible block-wide
    const int d   = t;
    const int b   = m0 >> 13;                 // batch
    const int s32 = (m0 & (LSZ - 1)) >> 5;    // first 32-seg index
    const __half* __restrict__ Z = g_proj[dir * 3 + 0];
    const __half* __restrict__ H = g_proj[dir * 3 + 1];

    #pragma unroll
    for (int part = 0; part < 4; part++) {
        float A = 1.0f, Bc = 0.0f;
        #pragma unroll 4
        for (int i = 0; i < SEGL; i++) {
            int rr = dir ? (SEGL - 1 - i) : i;   // bwd composes descending
            size_t idx = (size_t)(m0 + part * SEGL + rr) * DSZ + d;
            float z  = __half2float(Z[idx]);
            float ht = __half2float(H[idx]);
            float a = 1.0f - z;
            A = A * a;
            Bc = fmaf(a, Bc, z * ht);
        }
        int segidx = dir ? (NSEG2 - 1 - (s32 + part)) : (s32 + part);
        size_t o = (((size_t)dir * BSZ + b) * NSEG2 + segidx) * DSZ + d;
        g_segA[o] = A;
        g_segB[o] = Bc;
    }
}

// ---------------------------------------------------------------------------
// Scan pass 2: sequential combine over 256 segments; register-batched.
// grid (BSZ, 2), block DSZ
// ---------------------------------------------------------------------------
__global__ void scan_pass2(const float* __restrict__ h0f,
                           const float* __restrict__ h0b) {
    const int d   = threadIdx.x;
    const int b   = blockIdx.x;
    const int dir = blockIdx.y;
    float h = dir ? h0b[d] : h0f[d];
    size_t base = (((size_t)dir * BSZ + b) * NSEG2) * DSZ + d;
    for (int sc = 0; sc < NSEG2 / 16; sc++) {
        float rA[16], rB[16];
        #pragma unroll
        for (int s = 0; s < 16; s++) {
            size_t o = base + (size_t)(sc * 16 + s) * DSZ;
            rA[s] = g_segA[o];
            rB[s] = g_segB[o];
        }
        #pragma unroll
        for (int s = 0; s < 16; s++) {
            size_t o = base + (size_t)(sc * 16 + s) * DSZ;
            g_carry[o] = h;
            h = fmaf(rA[s], h, rB[s]);
        }
    }
}

// ---------------------------------------------------------------------------
// Scan out: both directions fused; fwd staged as fp16 in 16KB SMEM.
// grid (NSEG2, BSZ), block 128 (each thread owns 2 adjacent d channels)
// ---------------------------------------------------------------------------
__global__ void scan_out(float* __restrict__ out) {
    extern __shared__ __half2 sv[];           // [SEGL][128]
    const int d2  = threadIdx.x;              // channel pair: d = 2*d2, 2*d2+1
    const int seg = blockIdx.x;
    const int b   = blockIdx.y;
    const __half2* __restrict__ Zf = reinterpret_cast<const __half2*>(g_proj[0]);
    const __half2* __restrict__ Hf = reinterpret_cast<const __half2*>(g_proj[1]);
    const __half2* __restrict__ Sf = reinterpret_cast<const __half2*>(g_proj[2]);
    const __half2* __restrict__ Zb = reinterpret_cast<const __half2*>(g_proj[3]);
    const __half2* __restrict__ Hb = reinterpret_cast<const __half2*>(g_proj[4]);
    const __half2* __restrict__ Sb = reinterpret_cast<const __half2*>(g_proj[5]);

    // half2-granular row base: row * 128 + d2
    size_t rowbase = ((size_t)b * LSZ + (size_t)seg * SEGL) * 128 + d2;

    // forward
    float2 h = *reinterpret_cast<const float2*>(
        &g_carry[(((size_t)b) * NSEG2 + seg) * DSZ + 2 * d2]);
    #pragma unroll 4
    for (int i = 0; i < SEGL; i++) {
        size_t idx = rowbase + (size_t)i * 128;
        float2 z = __half22float2(Zf[idx]);
        float2 ht = __half22float2(Hf[idx]);
        float2 s = __half22float2(Sf[idx]);
        h.x = fmaf(1.0f - z.x, h.x, z.x * ht.x);
        h.y = fmaf(1.0f - z.y, h.y, z.y * ht.y);
        sv[i * 128 + d2] = __floats2half2_rn(h.x * s.x, h.y * s.y);
    }
    // backward: these rows reversed form bwd segment NSEG2-1-seg
    float2 hb = *reinterpret_cast<const float2*>(
        &g_carry[(((size_t)BSZ + b) * NSEG2 + (NSEG2 - 1 - seg)) * DSZ + 2 * d2]);
    #pragma unroll 4
    for (int jj = 0; jj < SEGL; jj++) {
        int i = SEGL - 1 - jj;
        size_t idx = rowbase + (size_t)i * 128;
        float2 z = __half22float2(Zb[idx]);
        float2 ht = __half22float2(Hb[idx]);
        float2 s = __half22float2(Sb[idx]);
        hb.x = fmaf(1.0f - z.x, hb.x, z.x * ht.x);
        hb.y = fmaf(1.0f - z.y, hb.y, z.y * ht.y);
        float2 v = __half22float2(sv[i * 128 + d2]);
        v.x = fmaf(hb.x, s.x, v.x);
        v.y = fmaf(hb.y, s.y, v.y);
        *reinterpret_cast<float2*>(&out[idx * 2]) = v;
    }
}

// ---------------------------------------------------------------------------
// Launch. Inputs: 0 xs, 1 Wh1, 2 bh1, 3 Wz1, 4 bz1, 5 Ws1, 6 bs1, 7 h01,
//   8 Wh_1, 9 bh_1, 10 Wz_1, 11 bz_1, 12 Ws_1, 13 bs_1, 14 h0_1
// ---------------------------------------------------------------------------
extern "C" void kernel_launch(void* const* d_in, const int* in_sizes, int n_in,
                              void* d_out, int out_size) {
    cudaFuncSetAttribute(gemm_fused,
                         cudaFuncAttributeMaxDynamicSharedMemorySize, GEMM_SMEM);

    // widx: 0=z_f(Wz1), 1=h_f(Wh1), 2=s_f(Ws1), 3=z_b(Wz_1), 4=h_b(Wh_1), 5=s_b(Ws_1)
    WPtrs wp;
    wp.W[0] = (const float*)d_in[3];
    wp.W[1] = (const float*)d_in[1];
    wp.W[2] = (const float*)d_in[5];
    wp.W[3] = (const float*)d_in[10];
    wp.W[4] = (const float*)d_in[8];
    wp.W[5] = (const float*)d_in[12];
    BiasPtrs bp;
    bp.b[0] = (const float*)d_in[4];
    bp.b[1] = (const float*)d_in[2];
    bp.b[2] = (const float*)d_in[6];
    bp.b[3] = (const float*)d_in[11];
    bp.b[4] = (const float*)d_in[9];
    bp.b[5] = (const float*)d_in[13];

    prep_w<<<dim3(6, 256), 256>>>(wp);
    gemm_fused<<<dim3(MSZ / MT, 2), 256, GEMM_SMEM>>>(bp, (const float*)d_in[0]);
    scan_pass2<<<dim3(BSZ, 2), DSZ>>>((const float*)d_in[7], (const float*)d_in[14]);
    scan_out<<<dim3(NSEG2, BSZ), 128, SEGL * 128 * sizeof(__half2)>>>((float*)d_out);
}